// round 5
// baseline (speedup 1.0000x reference)
#include <cuda_runtime.h>
#include <cstdint>

#define B_    128
#define F_    64
#define KTOT  (2048 * 512)     // 1048576
#define CHUNK 2048             // K per CTA
#define TILES 64               // CHUNK / 32

// dynamic smem layout (float offsets)
#define A_OFF  0               // 4 stages x (128 rows x 32 k) = 16384 floats (raw fp32)
#define V_OFF  16384           // 2 bufs x (64 f x 32 k) = 4096 (tf32 bits)
#define UA_OFF 20480           // 4 rows x 256 = 1024
#define SMEM_FLOATS 21504      // 86016 bytes

static __device__ __forceinline__ uint32_t s2u(const void* p) {
    uint32_t a;
    asm("{ .reg .u64 t; cvta.to.shared.u64 t, %1; cvt.u32.u64 %0, t; }" : "=r"(a) : "l"(p));
    return a;
}
static __device__ __forceinline__ uint32_t f2tf32(float x) {
    uint32_t r;
    asm("cvt.rna.tf32.f32 %0, %1;" : "=r"(r) : "f"(x));
    return r;
}
static __device__ __forceinline__ void mma_tf32(float c[4], const uint32_t a[4],
                                                uint32_t b0, uint32_t b1) {
    asm volatile(
        "mma.sync.aligned.m16n8k8.row.col.f32.tf32.tf32.f32 "
        "{%0,%1,%2,%3}, {%4,%5,%6,%7}, {%8,%9}, {%0,%1,%2,%3};"
        : "+f"(c[0]), "+f"(c[1]), "+f"(c[2]), "+f"(c[3])
        : "r"(a[0]), "r"(a[1]), "r"(a[2]), "r"(a[3]), "r"(b0), "r"(b1));
}

__global__ void zero_out_kernel(float* out) {
    out[blockIdx.x * 256 + threadIdx.x] = 0.0f;
}

// out[b,f] = sum_k jac[b,k] * V[k,f], k=(i,j), V = sum_r Ua[i,r,f]*Ub[j,r,f]
// CTA covers 4 i-rows x 512 j-cols (2048 k). Tiles: jt outer (16) x ii inner (4).
template <int M2>
__device__ __forceinline__ void hora_body(
    const float* __restrict__ jac, const float* __restrict__ Ua,
    const float* __restrict__ Ub, float* __restrict__ out, float* sm)
{
    float* Asm = sm + A_OFF;
    float* Vsm = sm + V_OFF;
    float* Uas = sm + UA_OFF;
    const uint32_t smA = s2u(Asm);

    const int tid  = threadIdx.x;           // 256
    const int wid  = tid >> 5;
    const int lane = tid & 31;
    const int g    = lane >> 2;             // 0..7
    const int t4   = lane & 3;              // 0..3
    const int wm   = (wid & 3) * 32;
    const int wn   = (wid >> 2) * 32;

    int i0, j0;
    if (M2 == 512) { i0 = blockIdx.x * 4;        j0 = 0; }
    else           { i0 = (blockIdx.x >> 2) * 4; j0 = (blockIdx.x & 3) * 512; }

    // staging roles
    const int arow = tid >> 1;              // jac row, 2 threads/row
    const int ac0  = (tid & 1) * 4;         // first of 4 16B chunks
    const int f    = tid & 63;              // V producer: one f column
    const int kg   = tid >> 6;              // V producer: k-group (8 k's)

    // ---- Ua preload: 4 rows x 256 floats = 1024 ----
    {
        float4 v = *reinterpret_cast<const float4*>(Ua + (size_t)i0 * 256 + tid * 4);
        *reinterpret_cast<float4*>(Uas + tid * 4) = v;
    }

    float ubr[8][4];
    float acc[2][4][4];
    #pragma unroll
    for (int m = 0; m < 2; m++)
        #pragma unroll
        for (int n = 0; n < 4; n++)
            #pragma unroll
            for (int e = 0; e < 4; e++) acc[m][n][e] = 0.0f;

    #define CP_A(T) do {                                                        \
        size_t koff_ = (size_t)(i0 + ((T) & 3)) * M2 + j0 +                     \
                       (size_t)((T) >> 2) * 32;                                 \
        const float* src_ = jac + (size_t)arow * KTOT + koff_ + ac0 * 4;        \
        uint32_t dstb_ = smA + ((((T) & 3) * 4096 + arow * 32) << 2);           \
        _Pragma("unroll")                                                       \
        for (int q_ = 0; q_ < 4; q_++) {                                        \
            uint32_t d_ = dstb_ + (uint32_t)(((ac0 + q_) ^ (arow & 7)) * 16);   \
            asm volatile("cp.async.cg.shared.global [%0], [%1], 16;"            \
                         :: "r"(d_), "l"(src_ + q_ * 4) : "memory");            \
        }                                                                       \
    } while (0)
    #define CP_COMMIT() asm volatile("cp.async.commit_group;" ::: "memory")
    #define CP_WAIT2()  asm volatile("cp.async.wait_group 2;" ::: "memory")

    #define LOAD_UB(JT) do {                                                    \
        const float* p_ = Ub + (size_t)(j0 + (JT) * 32 + kg * 8) * 256 + f;     \
        _Pragma("unroll")                                                       \
        for (int q_ = 0; q_ < 8; q_++)                                          \
            _Pragma("unroll")                                                   \
            for (int r_ = 0; r_ < 4; r_++)                                      \
                ubr[q_][r_] = __ldg(p_ + q_ * 256 + r_ * 64);                   \
    } while (0)

    #define PRODUCE_V(TT) do {                                                  \
        const float* ua_ = Uas + ((TT) & 3) * 256 + f;                          \
        float a0_ = ua_[0], a1_ = ua_[64], a2_ = ua_[128], a3_ = ua_[192];      \
        uint32_t v_[8];                                                         \
        _Pragma("unroll")                                                       \
        for (int q_ = 0; q_ < 8; q_++)                                          \
            v_[q_] = f2tf32(a0_ * ubr[q_][0] + a1_ * ubr[q_][1] +               \
                            a2_ * ubr[q_][2] + a3_ * ubr[q_][3]);               \
        uint4* vb_ = reinterpret_cast<uint4*>(Vsm + ((TT) & 1) * 2048 + f * 32);\
        uint4 w0_ = {v_[0], v_[1], v_[2], v_[3]};                               \
        uint4 w1_ = {v_[4], v_[5], v_[6], v_[7]};                               \
        vb_[(2 * kg)     ^ (f & 7)] = w0_;                                      \
        vb_[(2 * kg + 1) ^ (f & 7)] = w1_;                                      \
    } while (0)

    // ---- prologue: fill 3 stages, first Ub slice, V[0] ----
    CP_A(0); CP_COMMIT();
    CP_A(1); CP_COMMIT();
    CP_A(2); CP_COMMIT();
    LOAD_UB(0);
    __syncthreads();                        // Ua visible
    PRODUCE_V(0);

    // ---- main loop ----
    for (int t = 0; t < TILES; t++) {
        CP_WAIT2();                         // A[t] arrived (this thread's part)
        __syncthreads();                    // publish A[t] + V[t]; drain readers of t-1
        if (t + 3 < TILES) CP_A(t + 3);     // recycle stage (t-1)&3 — safe post-sync
        CP_COMMIT();
        if (((t + 1) & 3) == 0 && (t + 1) < TILES)
            LOAD_UB((t + 1) >> 2);          // L2 latency overlapped by MMA phase

        // MMA on tile t
        {
            const float*    Ab = Asm + (t & 3) * 4096;
            const uint32_t* Vb = reinterpret_cast<const uint32_t*>(Vsm + (t & 1) * 2048);
            #pragma unroll
            for (int ks = 0; ks < 4; ks++) {
                uint32_t a[2][4];
                const int c0 = ks * 8 + t4;
                const int c1 = c0 + 4;
                const int sw = 4 * g;
                #pragma unroll
                for (int m = 0; m < 2; m++) {
                    const int r0 = wm + m * 16 + g;
                    const int r1 = r0 + 8;
                    a[m][0] = f2tf32(Ab[r0 * 32 + (c0 ^ sw)]);
                    a[m][1] = f2tf32(Ab[r1 * 32 + (c0 ^ sw)]);
                    a[m][2] = f2tf32(Ab[r0 * 32 + (c1 ^ sw)]);
                    a[m][3] = f2tf32(Ab[r1 * 32 + (c1 ^ sw)]);
                }
                const int kr0 = c0;         // ks*8 + t4
                const int kr1 = c1;
                #pragma unroll
                for (int n = 0; n < 4; n++) {
                    const int col = wn + n * 8 + g;
                    uint32_t b0 = Vb[col * 32 + (kr0 ^ sw)];
                    uint32_t b1 = Vb[col * 32 + (kr1 ^ sw)];
                    mma_tf32(acc[0][n], a[0], b0, b1);
                    mma_tf32(acc[1][n], a[1], b0, b1);
                }
            }
        }

        if (t + 1 < TILES) PRODUCE_V(t + 1);   // writes buf (t+1)&1, readers of t-1 drained
    }
    #undef CP_A
    #undef CP_COMMIT
    #undef CP_WAIT2
    #undef LOAD_UB
    #undef PRODUCE_V

    // ---- epilogue ----
    #pragma unroll
    for (int m = 0; m < 2; m++) {
        #pragma unroll
        for (int n = 0; n < 4; n++) {
            const int row = wm + m * 16 + g;
            const int col = wn + n * 8 + t4 * 2;
            atomicAdd(&out[row * F_ + col],           acc[m][n][0]);
            atomicAdd(&out[row * F_ + col + 1],       acc[m][n][1]);
            atomicAdd(&out[(row + 8) * F_ + col],     acc[m][n][2]);
            atomicAdd(&out[(row + 8) * F_ + col + 1], acc[m][n][3]);
        }
    }
}

__global__ void __launch_bounds__(256, 2)
hora_kernel(const float* __restrict__ jac1, const float* __restrict__ U1a,
            const float* __restrict__ U1b,  const float* __restrict__ jac2,
            const float* __restrict__ U2a,  const float* __restrict__ U2b,
            float* __restrict__ out)
{
    extern __shared__ float smf[];
    if (blockIdx.y == 0)
        hora_body<512>(jac1, U1a, U1b, out, smf);    // jac1 [B, i=2048, j=512]
    else
        hora_body<2048>(jac2, U2a, U2b, out, smf);   // jac2 [B, i=512, j=2048]
}

extern "C" void kernel_launch(void* const* d_in, const int* in_sizes, int n_in,
                              void* d_out, int out_size) {
    const float* jac1 = (const float*)d_in[0];
    const float* jac2 = (const float*)d_in[1];
    const float* U1a  = (const float*)d_in[2];
    const float* U1b  = (const float*)d_in[3];
    const float* U2a  = (const float*)d_in[4];
    const float* U2b  = (const float*)d_in[5];
    float* out = (float*)d_out;

    cudaFuncSetAttribute(hora_kernel,
                         cudaFuncAttributeMaxDynamicSharedMemorySize,
                         SMEM_FLOATS * 4);

    zero_out_kernel<<<(B_ * F_) / 256, 256>>>(out);
    hora_kernel<<<dim3(512, 2), 256, SMEM_FLOATS * 4>>>(
        jac1, U1a, U1b, jac2, U2a, U2b, out);
}

// round 6
// speedup vs baseline: 1.0035x; 1.0035x over previous
#include <cuda_runtime.h>
#include <cstdint>

#define B_    128
#define F_    64
#define KTOT  (2048 * 512)     // 1048576
#define CHUNK 2048             // K per CTA
#define TILES 64               // CHUNK / 32

// dynamic smem layout (float offsets)
#define A_OFF  0               // 4 stages x (128 rows x 32 k) = 16384 floats (raw fp32)
#define V_OFF  16384           // 2 bufs x (64 f x 32 k) = 4096 (tf32 bits)
#define UA_OFF 20480           // 4 rows x 256 = 1024
#define SMEM_FLOATS 21504      // 86016 bytes

static __device__ __forceinline__ uint32_t s2u(const void* p) {
    uint32_t a;
    asm("{ .reg .u64 t; cvta.to.shared.u64 t, %1; cvt.u32.u64 %0, t; }" : "=r"(a) : "l"(p));
    return a;
}
static __device__ __forceinline__ uint32_t f2tf32(float x) {
    uint32_t r;
    asm("cvt.rna.tf32.f32 %0, %1;" : "=r"(r) : "f"(x));
    return r;
}
static __device__ __forceinline__ void mma_tf32(float c[4], const uint32_t a[4],
                                                uint32_t b0, uint32_t b1) {
    asm volatile(
        "mma.sync.aligned.m16n8k8.row.col.f32.tf32.tf32.f32 "
        "{%0,%1,%2,%3}, {%4,%5,%6,%7}, {%8,%9}, {%0,%1,%2,%3};"
        : "+f"(c[0]), "+f"(c[1]), "+f"(c[2]), "+f"(c[3])
        : "r"(a[0]), "r"(a[1]), "r"(a[2]), "r"(a[3]), "r"(b0), "r"(b1));
}

__global__ void zero_out_kernel(float* out) {
    out[blockIdx.x * 256 + threadIdx.x] = 0.0f;
}

// out[b,f] = sum_k jac[b,k] * V[k,f], k=(i,j), V = sum_r Ua[i,r,f]*Ub[j,r,f]
// CTA covers 4 i-rows x 512 j-cols (2048 k). Tiles: jt outer (16) x ii inner (4).
template <int M2>
__device__ __forceinline__ void hora_body(
    const float* __restrict__ jac, const float* __restrict__ Ua,
    const float* __restrict__ Ub, float* __restrict__ out, float* sm)
{
    float* Asm = sm + A_OFF;
    float* Vsm = sm + V_OFF;
    float* Uas = sm + UA_OFF;
    const uint32_t smA = s2u(Asm);

    const int tid  = threadIdx.x;           // 256
    const int wid  = tid >> 5;
    const int lane = tid & 31;
    const int g    = lane >> 2;             // 0..7
    const int t4   = lane & 3;              // 0..3
    const int wm   = (wid & 3) * 32;
    const int wn   = (wid >> 2) * 32;

    int i0, j0;
    if (M2 == 512) { i0 = blockIdx.x * 4;        j0 = 0; }
    else           { i0 = (blockIdx.x >> 2) * 4; j0 = (blockIdx.x & 3) * 512; }

    // staging roles
    const int arow = tid >> 1;              // jac row, 2 threads/row
    const int ac0  = (tid & 1) * 4;         // first of 4 16B chunks
    const int f    = tid & 63;              // V producer: one f column
    const int kg   = tid >> 6;              // V producer: k-group (8 k's)

    // ---- Ua preload: 4 rows x 256 floats = 1024 ----
    {
        float4 v = *reinterpret_cast<const float4*>(Ua + (size_t)i0 * 256 + tid * 4);
        *reinterpret_cast<float4*>(Uas + tid * 4) = v;
    }

    float ubr[8][4];
    float acc[2][4][4];
    #pragma unroll
    for (int m = 0; m < 2; m++)
        #pragma unroll
        for (int n = 0; n < 4; n++)
            #pragma unroll
            for (int e = 0; e < 4; e++) acc[m][n][e] = 0.0f;

    #define CP_A(T) do {                                                        \
        size_t koff_ = (size_t)(i0 + ((T) & 3)) * M2 + j0 +                     \
                       (size_t)((T) >> 2) * 32;                                 \
        const float* src_ = jac + (size_t)arow * KTOT + koff_ + ac0 * 4;        \
        uint32_t dstb_ = smA + ((((T) & 3) * 4096 + arow * 32) << 2);           \
        _Pragma("unroll")                                                       \
        for (int q_ = 0; q_ < 4; q_++) {                                        \
            uint32_t d_ = dstb_ + (uint32_t)(((ac0 + q_) ^ (arow & 7)) * 16);   \
            asm volatile("cp.async.cg.shared.global [%0], [%1], 16;"            \
                         :: "r"(d_), "l"(src_ + q_ * 4) : "memory");            \
        }                                                                       \
    } while (0)
    #define CP_COMMIT() asm volatile("cp.async.commit_group;" ::: "memory")
    #define CP_WAIT2()  asm volatile("cp.async.wait_group 2;" ::: "memory")

    #define LOAD_UB(JT) do {                                                    \
        const float* p_ = Ub + (size_t)(j0 + (JT) * 32 + kg * 8) * 256 + f;     \
        _Pragma("unroll")                                                       \
        for (int q_ = 0; q_ < 8; q_++)                                          \
            _Pragma("unroll")                                                   \
            for (int r_ = 0; r_ < 4; r_++)                                      \
                ubr[q_][r_] = __ldg(p_ + q_ * 256 + r_ * 64);                   \
    } while (0)

    #define PRODUCE_V(TT) do {                                                  \
        const float* ua_ = Uas + ((TT) & 3) * 256 + f;                          \
        float a0_ = ua_[0], a1_ = ua_[64], a2_ = ua_[128], a3_ = ua_[192];      \
        uint32_t v_[8];                                                         \
        _Pragma("unroll")                                                       \
        for (int q_ = 0; q_ < 8; q_++)                                          \
            v_[q_] = f2tf32(a0_ * ubr[q_][0] + a1_ * ubr[q_][1] +               \
                            a2_ * ubr[q_][2] + a3_ * ubr[q_][3]);               \
        uint4* vb_ = reinterpret_cast<uint4*>(Vsm + ((TT) & 1) * 2048 + f * 32);\
        uint4 w0_ = {v_[0], v_[1], v_[2], v_[3]};                               \
        uint4 w1_ = {v_[4], v_[5], v_[6], v_[7]};                               \
        vb_[(2 * kg)     ^ (f & 7)] = w0_;                                      \
        vb_[(2 * kg + 1) ^ (f & 7)] = w1_;                                      \
    } while (0)

    // ---- prologue: fill 3 stages, first Ub slice, V[0] ----
    CP_A(0); CP_COMMIT();
    CP_A(1); CP_COMMIT();
    CP_A(2); CP_COMMIT();
    LOAD_UB(0);
    __syncthreads();                        // Ua visible
    PRODUCE_V(0);

    // ---- main loop ----
    for (int t = 0; t < TILES; t++) {
        CP_WAIT2();                         // A[t] arrived (this thread's part)
        __syncthreads();                    // publish A[t] + V[t]; drain readers of t-1
        if (t + 3 < TILES) CP_A(t + 3);     // recycle stage (t-1)&3 — safe post-sync
        CP_COMMIT();
        if (((t + 1) & 3) == 0 && (t + 1) < TILES)
            LOAD_UB((t + 1) >> 2);          // L2 latency overlapped by MMA phase

        // MMA on tile t
        {
            const float*    Ab = Asm + (t & 3) * 4096;
            const uint32_t* Vb = reinterpret_cast<const uint32_t*>(Vsm + (t & 1) * 2048);
            #pragma unroll
            for (int ks = 0; ks < 4; ks++) {
                uint32_t a[2][4];
                const int c0 = ks * 8 + t4;
                const int c1 = c0 + 4;
                const int sw = 4 * g;
                #pragma unroll
                for (int m = 0; m < 2; m++) {
                    const int r0 = wm + m * 16 + g;
                    const int r1 = r0 + 8;
                    a[m][0] = f2tf32(Ab[r0 * 32 + (c0 ^ sw)]);
                    a[m][1] = f2tf32(Ab[r1 * 32 + (c0 ^ sw)]);
                    a[m][2] = f2tf32(Ab[r0 * 32 + (c1 ^ sw)]);
                    a[m][3] = f2tf32(Ab[r1 * 32 + (c1 ^ sw)]);
                }
                const int kr0 = c0;         // ks*8 + t4
                const int kr1 = c1;
                #pragma unroll
                for (int n = 0; n < 4; n++) {
                    const int col = wn + n * 8 + g;
                    uint32_t b0 = Vb[col * 32 + (kr0 ^ sw)];
                    uint32_t b1 = Vb[col * 32 + (kr1 ^ sw)];
                    mma_tf32(acc[0][n], a[0], b0, b1);
                    mma_tf32(acc[1][n], a[1], b0, b1);
                }
            }
        }

        if (t + 1 < TILES) PRODUCE_V(t + 1);   // writes buf (t+1)&1, readers of t-1 drained
    }
    #undef CP_A
    #undef CP_COMMIT
    #undef CP_WAIT2
    #undef LOAD_UB
    #undef PRODUCE_V

    // ---- epilogue ----
    #pragma unroll
    for (int m = 0; m < 2; m++) {
        #pragma unroll
        for (int n = 0; n < 4; n++) {
            const int row = wm + m * 16 + g;
            const int col = wn + n * 8 + t4 * 2;
            atomicAdd(&out[row * F_ + col],           acc[m][n][0]);
            atomicAdd(&out[row * F_ + col + 1],       acc[m][n][1]);
            atomicAdd(&out[(row + 8) * F_ + col],     acc[m][n][2]);
            atomicAdd(&out[(row + 8) * F_ + col + 1], acc[m][n][3]);
        }
    }
}

__global__ void __launch_bounds__(256, 2)
hora_kernel(const float* __restrict__ jac1, const float* __restrict__ U1a,
            const float* __restrict__ U1b,  const float* __restrict__ jac2,
            const float* __restrict__ U2a,  const float* __restrict__ U2b,
            float* __restrict__ out)
{
    extern __shared__ float smf[];
    if (blockIdx.y == 0)
        hora_body<512>(jac1, U1a, U1b, out, smf);    // jac1 [B, i=2048, j=512]
    else
        hora_body<2048>(jac2, U2a, U2b, out, smf);   // jac2 [B, i=512, j=2048]
}

extern "C" void kernel_launch(void* const* d_in, const int* in_sizes, int n_in,
                              void* d_out, int out_size) {
    const float* jac1 = (const float*)d_in[0];
    const float* jac2 = (const float*)d_in[1];
    const float* U1a  = (const float*)d_in[2];
    const float* U1b  = (const float*)d_in[3];
    const float* U2a  = (const float*)d_in[4];
    const float* U2b  = (const float*)d_in[5];
    float* out = (float*)d_out;

    cudaFuncSetAttribute(hora_kernel,
                         cudaFuncAttributeMaxDynamicSharedMemorySize,
                         SMEM_FLOATS * 4);

    zero_out_kernel<<<(B_ * F_) / 256, 256>>>(out);
    hora_kernel<<<dim3(512, 2), 256, SMEM_FLOATS * 4>>>(
        jac1, U1a, U1b, jac2, U2a, U2b, out);
}